// round 15
// baseline (speedup 1.0000x reference)
#include <cuda_runtime.h>
#include <stdint.h>

#define NNODES 50000
#define NEDGES 800000
#define NPAIRS 200000
#define DIN    256
#define H1DIM  512
#define H2DIM  256
#define H3DIM  160
#define NROWS_PAIR (2*NPAIRS)
#define SCAN_BLOCKS ((NNODES + 255) / 256)   // 196
#define EDGE_BLOCKS ((NEDGES + 255) / 256)   // 3125

// ---------------- scratch (static device globals; no allocation) -------------
__device__ int   g_cnt[2 * NNODES];          // [0..N) out-deg, [N..2N) in-deg
__device__ float g_onorm[NNODES];
__device__ float g_inorm[NNODES];
__device__ int   g_bsum[SCAN_BLOCKS];
__device__ int   g_rowptr[NNODES + 1];
__device__ int   g_cursor[NNODES];
__device__ int   g_csr_src[NEDGES];
__device__ float g_csr_w[NEDGES];
__device__ float g_bufA[(size_t)NNODES * 512];
__device__ float g_bufB[(size_t)NNODES * 512];
__device__ float g_bufC[(size_t)NNODES * 256];
__device__ float g_Wt[512*256 + 256*512 + 160*256 + 80*160 + 40*80];

// ---------------- helpers -----------------------------------------------------
static __device__ __forceinline__ float tf32r(float x) {
    uint32_t t;
    asm("cvt.rna.tf32.f32 %0, %1;" : "=r"(t) : "f"(x));
    return __uint_as_float(t);
}
static __device__ __forceinline__ uint32_t smem_u32(const void* p) {
    uint32_t a;
    asm("{ .reg .u64 t; cvta.to.shared.u64 t, %1; cvt.u32.u64 %0, t; }" : "=r"(a) : "l"(p));
    return a;
}

// ---------------- preprocessing -----------------------------------------------
// merged launch: blocks [0, EDGE_BLOCKS) count degrees; remaining blocks
// transpose+tf32-round the 5 weight matrices (independent work, same wave).
#define TW1 (256*512)
#define TW2 (TW1 + 512*256)
#define TW3 (TW2 + 256*160)
#define TP1 (TW3 + 160*80)
#define TP2 (TP1 + 80*40)
#define TRANS_BLOCKS ((TP2 + 255) / 256)     // 901
__global__ void count_trans_kernel(const int* __restrict__ src, const int* __restrict__ dst,
                                   const float* __restrict__ W1, const float* __restrict__ W2,
                                   const float* __restrict__ W3, const float* __restrict__ P1,
                                   const float* __restrict__ P2, float* __restrict__ Wt)
{
    int b = blockIdx.x;
    if (b < EDGE_BLOCKS) {
        int i = b * 256 + threadIdx.x;
        if (i < NEDGES) {
            atomicAdd(&g_cnt[src[i]], 1);
            atomicAdd(&g_cnt[NNODES + dst[i]], 1);
        }
    } else {
        int i = (b - EDGE_BLOCKS) * 256 + threadIdx.x;
        if (i >= TP2) return;
        const float* Wsrc; int K, N, base, off;
        if (i < TW1)      { Wsrc = W1; K = 256; N = 512; base = 0;   off = i; }
        else if (i < TW2) { Wsrc = W2; K = 512; N = 256; base = TW1; off = i - TW1; }
        else if (i < TW3) { Wsrc = W3; K = 256; N = 160; base = TW2; off = i - TW2; }
        else if (i < TP1) { Wsrc = P1; K = 160; N = 80;  base = TW3; off = i - TW3; }
        else              { Wsrc = P2; K = 80;  N = 40;  base = TP1; off = i - TP1; }
        int k = off / N, n = off - k * N;
        Wt[base + n * K + k] = tf32r(Wsrc[off]);
    }
}

// phase 1: norms + per-block sums of in-degree
__global__ void scan_phase1()
{
    __shared__ int ws[8];
    int tid = threadIdx.x;
    int i = blockIdx.x * 256 + tid;
    int v = 0;
    if (i < NNODES) {
        v = g_cnt[NNODES + i];
        g_onorm[i] = rsqrtf(fmaxf((float)g_cnt[i], 1.0f));
        g_inorm[i] = rsqrtf(fmaxf((float)v, 1.0f));
    }
    int lane = tid & 31, wid = tid >> 5;
    int s = v;
    #pragma unroll
    for (int off = 16; off > 0; off >>= 1) s += __shfl_down_sync(0xFFFFFFFFu, s, off);
    if (lane == 0) ws[wid] = s;
    __syncthreads();
    if (tid == 0) {
        int t = 0;
        #pragma unroll
        for (int j = 0; j < 8; j++) t += ws[j];
        g_bsum[blockIdx.x] = t;
    }
}

// phase 2(+3 merged): each block reduces g_bsum[0..bid) itself, then scans its tile
__global__ void scan_phase3()
{
    __shared__ int ws[8];
    __shared__ int rs[8];
    __shared__ int s_off;
    const int tid = threadIdx.x, bid = blockIdx.x;
    const int lane = tid & 31, wid = tid >> 5;

    // block offset = sum g_bsum[0..bid)
    int bv = (tid < bid) ? g_bsum[tid] : 0;   // bid <= 195 < 256
    int r = bv;
    #pragma unroll
    for (int off = 16; off > 0; off >>= 1) r += __shfl_down_sync(0xFFFFFFFFu, r, off);
    if (lane == 0) rs[wid] = r;
    __syncthreads();
    if (tid == 0) {
        int t = 0;
        #pragma unroll
        for (int j = 0; j < 8; j++) t += rs[j];
        s_off = t;
    }

    // per-tile exclusive scan
    int i = bid * 256 + tid;
    int v = (i < NNODES) ? g_cnt[NNODES + i] : 0;
    int x = v;
    #pragma unroll
    for (int off = 1; off < 32; off <<= 1) {
        int y = __shfl_up_sync(0xFFFFFFFFu, x, off);
        if (lane >= off) x += y;
    }
    if (lane == 31) ws[wid] = x;
    __syncthreads();
    if (wid == 0) {
        int s = (lane < 8) ? ws[lane] : 0;
        #pragma unroll
        for (int off = 1; off < 8; off <<= 1) {
            int y = __shfl_up_sync(0xFFFFFFFFu, s, off);
            if (lane >= off) s += y;
        }
        if (lane < 8) ws[lane] = s;
    }
    __syncthreads();
    int base = (wid > 0) ? ws[wid - 1] : 0;
    int e = base + x - v + s_off;
    if (i < NNODES) { g_rowptr[i] = e; g_cursor[i] = e; }
    if (i == 0) g_rowptr[NNODES] = NEDGES;
}

__global__ void fill_kernel(const int* __restrict__ src, const int* __restrict__ dst,
                            const float* __restrict__ w, int E)
{
    int i = blockIdx.x * blockDim.x + threadIdx.x;
    if (i < E) {
        int s = src[i];
        int slot = atomicAdd(&g_cursor[dst[i]], 1);
        g_csr_src[slot] = s;
        g_csr_w[slot]   = w[i] * g_onorm[s];
    }
}

// ---------------- CSR aggregation with fused epilogues ------------------------
// EPI: 0 = tf32-round(acc); 1 = tf32-round(relu(acc*inorm+bias)); 2 = acc*inorm+bias
template<int D, int EPI>
__global__ void csr_agg_kernel(const float* __restrict__ feat, float* __restrict__ outp,
                               const float* __restrict__ bias)
{
    const int node = (blockIdx.x * blockDim.x + threadIdx.x) >> 5;
    const int lane = threadIdx.x & 31;
    if (node >= NNODES) return;
    const int beg = g_rowptr[node], end = g_rowptr[node + 1];

    constexpr int NV = D / 4;
    constexpr bool HAS2 = (NV > 32);
    float4 acc0 = make_float4(0.f, 0.f, 0.f, 0.f);
    float4 acc1 = make_float4(0.f, 0.f, 0.f, 0.f);
    const bool use2 = HAS2 && (lane + 32 < NV);

    for (int base = beg; base < end; base += 32) {
        int cnt = min(32, end - base);
        int   sl = (lane < cnt) ? g_csr_src[base + lane] : 0;
        float wl = (lane < cnt) ? g_csr_w [base + lane] : 0.f;
        int j = 0;
        for (; j + 4 <= cnt; j += 4) {
            int   s0 = __shfl_sync(0xFFFFFFFFu, sl, j + 0);
            int   s1 = __shfl_sync(0xFFFFFFFFu, sl, j + 1);
            int   s2 = __shfl_sync(0xFFFFFFFFu, sl, j + 2);
            int   s3 = __shfl_sync(0xFFFFFFFFu, sl, j + 3);
            float w0 = __shfl_sync(0xFFFFFFFFu, wl, j + 0);
            float w1 = __shfl_sync(0xFFFFFFFFu, wl, j + 1);
            float w2 = __shfl_sync(0xFFFFFFFFu, wl, j + 2);
            float w3 = __shfl_sync(0xFFFFFFFFu, wl, j + 3);
            const float4* r0 = (const float4*)(feat + (size_t)s0 * D);
            const float4* r1 = (const float4*)(feat + (size_t)s1 * D);
            const float4* r2 = (const float4*)(feat + (size_t)s2 * D);
            const float4* r3 = (const float4*)(feat + (size_t)s3 * D);
            if (lane < NV) {
                float4 a0 = r0[lane], a1 = r1[lane], a2 = r2[lane], a3 = r3[lane];
                acc0.x += w0*a0.x + w1*a1.x + w2*a2.x + w3*a3.x;
                acc0.y += w0*a0.y + w1*a1.y + w2*a2.y + w3*a3.y;
                acc0.z += w0*a0.z + w1*a1.z + w2*a2.z + w3*a3.z;
                acc0.w += w0*a0.w + w1*a1.w + w2*a2.w + w3*a3.w;
            }
            if (use2) {
                float4 b0 = r0[lane+32], b1 = r1[lane+32], b2 = r2[lane+32], b3 = r3[lane+32];
                acc1.x += w0*b0.x + w1*b1.x + w2*b2.x + w3*b3.x;
                acc1.y += w0*b0.y + w1*b1.y + w2*b2.y + w3*b3.y;
                acc1.z += w0*b0.z + w1*b1.z + w2*b2.z + w3*b3.z;
                acc1.w += w0*b0.w + w1*b1.w + w2*b2.w + w3*b3.w;
            }
        }
        for (; j < cnt; j++) {
            int   s  = __shfl_sync(0xFFFFFFFFu, sl, j);
            float wv = __shfl_sync(0xFFFFFFFFu, wl, j);
            const float4* row = (const float4*)(feat + (size_t)s * D);
            if (lane < NV) {
                float4 a = row[lane];
                acc0.x += wv*a.x; acc0.y += wv*a.y; acc0.z += wv*a.z; acc0.w += wv*a.w;
            }
            if (use2) {
                float4 b = row[lane+32];
                acc1.x += wv*b.x; acc1.y += wv*b.y; acc1.z += wv*b.z; acc1.w += wv*b.w;
            }
        }
    }

    float nin = (EPI >= 1) ? g_inorm[node] : 1.0f;
    float4* orow = (float4*)(outp + (size_t)node * D);
    if (lane < NV) {
        float4 v = acc0;
        if (EPI >= 1) {
            float4 bb = *(const float4*)(bias + lane * 4);
            v.x = v.x * nin + bb.x; v.y = v.y * nin + bb.y;
            v.z = v.z * nin + bb.z; v.w = v.w * nin + bb.w;
            if (EPI == 1) {
                v.x = fmaxf(v.x, 0.f); v.y = fmaxf(v.y, 0.f);
                v.z = fmaxf(v.z, 0.f); v.w = fmaxf(v.w, 0.f);
            }
        }
        if (EPI != 2) { v.x = tf32r(v.x); v.y = tf32r(v.y); v.z = tf32r(v.z); v.w = tf32r(v.w); }
        orow[lane] = v;
    }
    if (use2) {
        float4 v = acc1;
        if (EPI >= 1) {
            float4 bb = *(const float4*)(bias + (lane + 32) * 4);
            v.x = v.x * nin + bb.x; v.y = v.y * nin + bb.y;
            v.z = v.z * nin + bb.z; v.w = v.w * nin + bb.w;
            if (EPI == 1) {
                v.x = fmaxf(v.x, 0.f); v.y = fmaxf(v.y, 0.f);
                v.z = fmaxf(v.z, 0.f); v.w = fmaxf(v.w, 0.f);
            }
        }
        if (EPI != 2) { v.x = tf32r(v.x); v.y = tf32r(v.y); v.z = tf32r(v.z); v.w = tf32r(v.w); }
        orow[lane + 32] = v;
    }
}

// ---------------- tf32 mma.sync GEMM (4 warps; 3-stage cp.async pipeline) -----
#define SROW 36
#define SBUF (128 * SROW)
#define MM_SMEM(NT) ((3 * SBUF + 3 * (NT) * SROW) * 4)

template<int EROW, int ACT, int ROUND, int NT>
__global__ __launch_bounds__(128)
void mm_gemm(const float* __restrict__ A, const float* __restrict__ Bt,
             float* __restrict__ C, int M, int K, int Nn,
             const float* __restrict__ escale, const float* __restrict__ cbias)
{
    constexpr int BS  = NT * SROW;
    constexpr int WNW = NT / 2;
    constexpr int NTFR = WNW / 8;
    extern __shared__ float smem[];
    float* sA = smem;                    // [3][SBUF]
    float* sB = smem + 3 * SBUF;         // [3][BS]
    const uint32_t sAu = smem_u32(sA);
    const uint32_t sBu = smem_u32(sB);

    const int tid  = threadIdx.x;
    const int m0   = blockIdx.y * 128;
    const int n0   = blockIdx.x * NT;
    const int lane = tid & 31;
    const int wq   = tid >> 5;
    const int wm   = wq & 1;
    const int wn   = wq >> 1;
    const int lr   = lane >> 2;
    const int lc   = lane & 3;
    const int sub  = lane >> 3;
    const int rr   = lane & 7;
    const int nch  = (K + 31) / 32;

    float acc[4][NTFR][4];
    #pragma unroll
    for (int mt = 0; mt < 4; mt++)
        #pragma unroll
        for (int nt = 0; nt < NTFR; nt++)
            #pragma unroll
            for (int r = 0; r < 4; r++) acc[mt][nt][r] = 0.0f;

    auto issue = [&](int c) {
        const int b = c % 3, k0 = c * 32;
        #pragma unroll
        for (int i = 0; i < 8; i++) {
            int idx = i * 128 + tid;
            int r = idx >> 3, kk = (idx & 7) * 4, gk = k0 + kk;
            uint32_t so = (uint32_t)(r * SROW + kk) * 4 + (uint32_t)b * (SBUF * 4);
            int gkc = min(gk, K - 4);
            int gm = m0 + r;
            int sz = ((gm < M) && (gk < K)) ? 16 : 0;
            const float* ga = A + (size_t)min(gm, M - 1) * K + gkc;
            asm volatile("cp.async.ca.shared.global [%0], [%1], 16, %2;"
                         :: "r"(sAu + so), "l"(ga), "r"(sz));
        }
        #pragma unroll
        for (int i = 0; i < NT / 16; i++) {
            int idx = i * 128 + tid;
            int r = idx >> 3, kk = (idx & 7) * 4, gk = k0 + kk;
            uint32_t so = (uint32_t)(r * SROW + kk) * 4 + (uint32_t)b * (BS * 4);
            int gkc = min(gk, K - 4);
            int gn = n0 + r;
            int szb = ((gn < Nn) && (gk < K)) ? 16 : 0;
            const float* gb = Bt + (size_t)min(gn, Nn - 1) * K + gkc;
            asm volatile("cp.async.ca.shared.global [%0], [%1], 16, %2;"
                         :: "r"(sBu + so), "l"(gb), "r"(szb));
        }
        asm volatile("cp.async.commit_group;" ::: "memory");
    };

    auto compute = [&](int b) {
        const uint32_t baseA = sAu + (uint32_t)b * (SBUF * 4);
        const uint32_t baseB = sBu + (uint32_t)b * (BS * 4);
        #pragma unroll
        for (int ks = 0; ks < 4; ks++) {
            const int kb = ks * 8;
            uint32_t af[4][4], bf[NTFR][2];
            #pragma unroll
            for (int mt = 0; mt < 4; mt++) {
                int row = wm * 64 + mt * 16 + rr + (sub & 1) * 8;
                int col = kb + (sub >> 1) * 4;
                uint32_t ad = baseA + (uint32_t)(row * SROW + col) * 4;
                asm volatile("ldmatrix.sync.aligned.m8n8.x4.shared.b16 {%0,%1,%2,%3}, [%4];"
                             : "=r"(af[mt][0]), "=r"(af[mt][1]), "=r"(af[mt][2]), "=r"(af[mt][3])
                             : "r"(ad));
            }
            #pragma unroll
            for (int ntp = 0; ntp < NTFR / 2; ntp++) {
                int row = wn * WNW + ntp * 16 + rr + (sub >> 1) * 8;
                int col = kb + (sub & 1) * 4;
                uint32_t bd = baseB + (uint32_t)(row * SROW + col) * 4;
                asm volatile("ldmatrix.sync.aligned.m8n8.x4.shared.b16 {%0,%1,%2,%3}, [%4];"
                             : "=r"(bf[2*ntp][0]), "=r"(bf[2*ntp][1]),
                               "=r"(bf[2*ntp+1][0]), "=r"(bf[2*ntp+1][1])
                             : "r"(bd));
            }
            #pragma unroll
            for (int mt = 0; mt < 4; mt++)
                #pragma unroll
                for (int nt = 0; nt < NTFR; nt++)
                    asm volatile(
                        "mma.sync.aligned.m16n8k8.row.col.f32.tf32.tf32.f32 "
                        "{%0,%1,%2,%3}, {%4,%5,%6,%7}, {%8,%9}, {%0,%1,%2,%3};"
                        : "+f"(acc[mt][nt][0]), "+f"(acc[mt][nt][1]),
                          "+f"(acc[mt][nt][2]), "+f"(acc[mt][nt][3])
                        : "r"(af[mt][0]), "r"(af[mt][1]), "r"(af[mt][2]), "r"(af[mt][3]),
                          "r"(bf[nt][0]), "r"(bf[nt][1]));
        }
    };

    // 3-stage pipeline, one barrier per chunk:
    // wait(group c) -> sync -> compute(c) -> issue(c+2)
    issue(0);
    if (nch > 1) issue(1);
    for (int c = 0; c < nch; c++) {
        if (c + 1 < nch) asm volatile("cp.async.wait_group 1;" ::: "memory");
        else             asm volatile("cp.async.wait_group 0;" ::: "memory");
        __syncthreads();
        compute(c % 3);
        if (c + 2 < nch) issue(c + 2);
    }

    #pragma unroll
    for (int mt = 0; mt < 4; mt++) {
        int r0 = m0 + wm * 64 + mt * 16 + lr;
        int r1 = r0 + 8;
        float s0 = 1.f, s1 = 1.f;
        if (EROW) {
            if (r0 < M) s0 = escale[r0];
            if (r1 < M) s1 = escale[r1];
        }
        #pragma unroll
        for (int nt = 0; nt < NTFR; nt++) {
            int col = n0 + wn * WNW + nt * 8 + lc * 2;
            if (col >= Nn) continue;
            float bx = 0.f, by = 0.f;
            if (cbias) { bx = cbias[col]; by = cbias[col + 1]; }
            #pragma unroll
            for (int half = 0; half < 2; half++) {
                int row = half ? r1 : r0;
                if (row >= M) continue;
                float sc = half ? s1 : s0;
                float vx = acc[mt][nt][half * 2 + 0] * sc + bx;
                float vy = acc[mt][nt][half * 2 + 1] * sc + by;
                if (ACT == 1) { vx = fmaxf(vx, 0.f); vy = fmaxf(vy, 0.f); }
                else if (ACT == 2) {
                    vx = (vx > 0.f) ? vx : 0.2f * vx;
                    vy = (vy > 0.f) ? vy : 0.2f * vy;
                }
                if (ROUND) { vx = tf32r(vx); vy = tf32r(vy); }
                *(float2*)(C + (size_t)row * Nn + col) = make_float2(vx, vy);
            }
        }
    }
}

// ---------------- fused predictor: pair-gather -> 160->80 -> 80->40 -> 40->1 --
#define PF_CH (128 * 36)
#define PF_SMEM_BYTES (5 * PF_CH * 4)   // 92160

__global__ __launch_bounds__(128)
void pred_fused(const float* __restrict__ h3,
                const float* __restrict__ P1t, const float* __restrict__ pb1,
                const float* __restrict__ P2t, const float* __restrict__ pb2,
                const float* __restrict__ P3,  const float* __restrict__ pb3,
                const int* __restrict__ ips, const int* __restrict__ ipd,
                const int* __restrict__ ins, const int* __restrict__ ind,
                float* __restrict__ out)
{
    extern __shared__ float smem[];
    float* sAd = smem;                 // [2][PF_CH]
    float* s1o = smem + 2 * PF_CH;     // [3][PF_CH]
    float* s2o = smem;                 // alias over sAd
    const uint32_t sAu = smem_u32(sAd);
    const uint32_t s1u = smem_u32(s1o);

    const int tid  = threadIdx.x;
    const int r0   = blockIdx.x * 128;
    const int lane = tid & 31;
    const int wq   = tid >> 5;
    const int wm   = wq & 1;
    const int wn   = wq >> 1;
    const int lr   = lane >> 2;
    const int lc   = lane & 3;
    const int sub  = lane >> 3;
    const int rr   = lane & 7;

    float4 rgA[8];
    auto fetchA = [&](int c) {
        const int k0 = c * 32;
        #pragma unroll
        for (int i = 0; i < 8; i++) {
            int idx = i * 128 + tid;
            int r = idx >> 3, kk = (idx & 7) * 4;
            int gm = r0 + r;
            int ia, ib;
            if (gm < NPAIRS) { ia = ips[gm]; ib = ipd[gm]; }
            else             { ia = ins[gm - NPAIRS]; ib = ind[gm - NPAIRS]; }
            float4 va = *(const float4*)(h3 + (size_t)ia * H3DIM + k0 + kk);
            float4 vb = *(const float4*)(h3 + (size_t)ib * H3DIM + k0 + kk);
            rgA[i] = make_float4(va.x*vb.x, va.y*vb.y, va.z*vb.z, va.w*vb.w);
        }
    };
    auto storeA = [&](int b) {
        #pragma unroll
        for (int i = 0; i < 8; i++) {
            int idx = i * 128 + tid;
            int r = idx >> 3, kk = (idx & 7) * 4;
            float4 v = rgA[i];
            v.x = tf32r(v.x); v.y = tf32r(v.y); v.z = tf32r(v.z); v.w = tf32r(v.w);
            *(float4*)(sAd + b * PF_CH + r * 36 + kk) = v;
        }
    };

    float a1[4][5][4];
    #pragma unroll
    for (int mt = 0; mt < 4; mt++)
        #pragma unroll
        for (int nt = 0; nt < 5; nt++)
            #pragma unroll
            for (int r = 0; r < 4; r++) a1[mt][nt][r] = 0.0f;

    auto compute1 = [&](int b, int c) {
        const uint32_t baseA = sAu + (uint32_t)b * (PF_CH * 4);
        #pragma unroll
        for (int ks = 0; ks < 4; ks++) {
            const int kb = ks * 8;
            const int kg = c * 32 + kb;
            uint32_t af[4][4], bf[5][2];
            #pragma unroll
            for (int mt = 0; mt < 4; mt++) {
                int row = wm * 64 + mt * 16 + rr + (sub & 1) * 8;
                int col = kb + (sub >> 1) * 4;
                uint32_t ad = baseA + (uint32_t)(row * 36 + col) * 4;
                asm volatile("ldmatrix.sync.aligned.m8n8.x4.shared.b16 {%0,%1,%2,%3}, [%4];"
                             : "=r"(af[mt][0]), "=r"(af[mt][1]), "=r"(af[mt][2]), "=r"(af[mt][3])
                             : "r"(ad));
            }
            #pragma unroll
            for (int nt = 0; nt < 5; nt++) {
                int n = wn * 40 + nt * 8 + lr;
                const float* bp = P1t + n * 160 + kg + lc;
                bf[nt][0] = __float_as_uint(__ldg(bp));
                bf[nt][1] = __float_as_uint(__ldg(bp + 4));
            }
            #pragma unroll
            for (int mt = 0; mt < 4; mt++)
                #pragma unroll
                for (int nt = 0; nt < 5; nt++)
                    asm volatile(
                        "mma.sync.aligned.m16n8k8.row.col.f32.tf32.tf32.f32 "
                        "{%0,%1,%2,%3}, {%4,%5,%6,%7}, {%8,%9}, {%0,%1,%2,%3};"
                        : "+f"(a1[mt][nt][0]), "+f"(a1[mt][nt][1]),
                          "+f"(a1[mt][nt][2]), "+f"(a1[mt][nt][3])
                        : "r"(af[mt][0]), "r"(af[mt][1]), "r"(af[mt][2]), "r"(af[mt][3]),
                          "r"(bf[nt][0]), "r"(bf[nt][1]));
        }
    };

    fetchA(0);
    storeA(0);
    for (int c = 0; c < 5; c++) {
        __syncthreads();
        if (c + 1 < 5) fetchA(c + 1);
        compute1(c & 1, c);
        if (c + 1 < 5) {
            __syncthreads();
            storeA((c + 1) & 1);
        }
    }

    #pragma unroll
    for (int mt = 0; mt < 4; mt++) {
        int row0 = wm * 64 + mt * 16 + lr;
        #pragma unroll
        for (int nt = 0; nt < 5; nt++) {
            int col = wn * 40 + nt * 8 + lc * 2;
            float bx = pb1[col], by = pb1[col + 1];
            int ch = col >> 5, ci = col & 31;
            #pragma unroll
            for (int half = 0; half < 2; half++) {
                int row = row0 + half * 8;
                float vx = a1[mt][nt][half * 2 + 0] + bx;
                float vy = a1[mt][nt][half * 2 + 1] + by;
                vx = (vx > 0.f) ? vx : 0.2f * vx;
                vy = (vy > 0.f) ? vy : 0.2f * vy;
                vx = tf32r(vx); vy = tf32r(vy);
                *(float2*)(s1o + ch * PF_CH + row * 36 + ci) = make_float2(vx, vy);
            }
        }
    }
    __syncthreads();

    float a2[2][5][4];
    #pragma unroll
    for (int mt = 0; mt < 2; mt++)
        #pragma unroll
        for (int nt = 0; nt < 5; nt++)
            #pragma unroll
            for (int r = 0; r < 4; r++) a2[mt][nt][r] = 0.0f;

    #pragma unroll
    for (int ch = 0; ch < 3; ch++) {
        const int nks = (ch < 2) ? 4 : 2;
        const uint32_t baseA = s1u + (uint32_t)ch * (PF_CH * 4);
        for (int ks = 0; ks < nks; ks++) {
            const int kb = ks * 8;
            const int kg = ch * 32 + kb;
            uint32_t af[2][4], bf[5][2];
            #pragma unroll
            for (int mt = 0; mt < 2; mt++) {
                int row = wq * 32 + mt * 16 + rr + (sub & 1) * 8;
                int col = kb + (sub >> 1) * 4;
                uint32_t ad = baseA + (uint32_t)(row * 36 + col) * 4;
                asm volatile("ldmatrix.sync.aligned.m8n8.x4.shared.b16 {%0,%1,%2,%3}, [%4];"
                             : "=r"(af[mt][0]), "=r"(af[mt][1]), "=r"(af[mt][2]), "=r"(af[mt][3])
                             : "r"(ad));
            }
            #pragma unroll
            for (int nt = 0; nt < 5; nt++) {
                int n = nt * 8 + lr;
                const float* bp = P2t + n * 80 + kg + lc;
                bf[nt][0] = __float_as_uint(__ldg(bp));
                bf[nt][1] = __float_as_uint(__ldg(bp + 4));
            }
            #pragma unroll
            for (int mt = 0; mt < 2; mt++)
                #pragma unroll
                for (int nt = 0; nt < 5; nt++)
                    asm volatile(
                        "mma.sync.aligned.m16n8k8.row.col.f32.tf32.tf32.f32 "
                        "{%0,%1,%2,%3}, {%4,%5,%6,%7}, {%8,%9}, {%0,%1,%2,%3};"
                        : "+f"(a2[mt][nt][0]), "+f"(a2[mt][nt][1]),
                          "+f"(a2[mt][nt][2]), "+f"(a2[mt][nt][3])
                        : "r"(af[mt][0]), "r"(af[mt][1]), "r"(af[mt][2]), "r"(af[mt][3]),
                          "r"(bf[nt][0]), "r"(bf[nt][1]));
        }
    }

    #pragma unroll
    for (int mt = 0; mt < 2; mt++) {
        int row0 = wq * 32 + mt * 16 + lr;
        #pragma unroll
        for (int nt = 0; nt < 5; nt++) {
            int col = nt * 8 + lc * 2;
            float bx = pb2[col], by = pb2[col + 1];
            #pragma unroll
            for (int half = 0; half < 2; half++) {
                int row = row0 + half * 8;
                float vx = a2[mt][nt][half * 2 + 0] + bx;
                float vy = a2[mt][nt][half * 2 + 1] + by;
                vx = (vx > 0.f) ? vx : 0.2f * vx;
                vy = (vy > 0.f) ? vy : 0.2f * vy;
                *(float2*)(s2o + row * 44 + col) = make_float2(vx, vy);
            }
        }
    }
    __syncthreads();

    float acc = __ldg(pb3);
    const float* rowp = s2o + tid * 44;
    #pragma unroll
    for (int k = 0; k < 40; k += 4) {
        float4 v = *(const float4*)(rowp + k);
        acc += v.x * __ldg(P3 + k + 0) + v.y * __ldg(P3 + k + 1)
             + v.z * __ldg(P3 + k + 2) + v.w * __ldg(P3 + k + 3);
    }
    out[r0 + tid] = acc;
}

// ---------------- launch ------------------------------------------------------
static inline dim3 mm_grid(int M, int Nn, int nt) { return dim3((Nn + nt - 1) / nt, (M + 127) / 128); }

extern "C" void kernel_launch(void* const* d_in, const int* in_sizes, int n_in,
                              void* d_out, int out_size)
{
    const float* x   = (const float*)d_in[0];
    const float* w   = (const float*)d_in[1];
    const int* src   = (const int*)d_in[2];
    const int* dst   = (const int*)d_in[3];
    const int* psrc  = (const int*)d_in[4];
    const int* pdst  = (const int*)d_in[5];
    const int* nsrc  = (const int*)d_in[6];
    const int* ndst  = (const int*)d_in[7];
    const float* W1  = (const float*)d_in[8];
    const float* b1  = (const float*)d_in[9];
    const float* W2  = (const float*)d_in[10];
    const float* b2  = (const float*)d_in[11];
    const float* W3  = (const float*)d_in[12];
    const float* b3  = (const float*)d_in[13];
    const float* P1  = (const float*)d_in[14];
    const float* pb1 = (const float*)d_in[15];
    const float* P2  = (const float*)d_in[16];
    const float* pb2 = (const float*)d_in[17];
    const float* P3  = (const float*)d_in[18];
    const float* pb3 = (const float*)d_in[19];

    float* out = (float*)d_out;
    float* out_h = out + NROWS_PAIR;   // [NPAIR pos | NPAIR neg | N*160 h]

    void *p_cnt, *p_inorm, *p_bufA, *p_bufB, *p_bufC, *p_Wt;
    cudaGetSymbolAddress(&p_cnt,   g_cnt);
    cudaGetSymbolAddress(&p_inorm, g_inorm);
    cudaGetSymbolAddress(&p_bufA,  g_bufA);
    cudaGetSymbolAddress(&p_bufB,  g_bufB);
    cudaGetSymbolAddress(&p_bufC,  g_bufC);
    cudaGetSymbolAddress(&p_Wt,    g_Wt);
    float* inorm = (float*)p_inorm;
    float* bufA = (float*)p_bufA;
    float* bufB = (float*)p_bufB;
    float* bufC = (float*)p_bufC;
    float* W1t = (float*)p_Wt;
    float* W2t = W1t + 512 * 256;
    float* W3t = W2t + 256 * 512;
    float* P1t = W3t + 160 * 256;
    float* P2t = P1t + 80 * 160;

    cudaFuncSetAttribute(mm_gemm<1,1,1,128>, cudaFuncAttributeMaxDynamicSharedMemorySize, MM_SMEM(128));
    cudaFuncSetAttribute(mm_gemm<0,0,0,128>, cudaFuncAttributeMaxDynamicSharedMemorySize, MM_SMEM(128));
    cudaFuncSetAttribute(mm_gemm<0,0,0,64>,  cudaFuncAttributeMaxDynamicSharedMemorySize, MM_SMEM(64));
    cudaFuncSetAttribute(pred_fused, cudaFuncAttributeMaxDynamicSharedMemorySize, PF_SMEM_BYTES);

    const int E = NEDGES;

    // ---- preprocessing: one memset; count+transpose merged; 2-kernel scan; fill
    cudaMemsetAsync(p_cnt, 0, 2 * NNODES * sizeof(int));
    count_trans_kernel<<<EDGE_BLOCKS + TRANS_BLOCKS, 256>>>(
        src, dst, W1, W2, W3, P1, P2, (float*)p_Wt);
    scan_phase1<<<SCAN_BLOCKS, 256>>>();
    scan_phase3<<<SCAN_BLOCKS, 256>>>();
    fill_kernel<<<(E + 255) / 256, 256>>>(src, dst, w, E);

    const int agg_blocks = (NNODES * 32 + 255) / 256;

    // ---- layer 1: agg(x) [round] -> GEMM1: @W1, *inorm+b1, relu, round
    csr_agg_kernel<DIN, 0><<<agg_blocks, 256>>>(x, bufA, nullptr);
    mm_gemm<1,1,1,128><<<mm_grid(NNODES, H1DIM, 128), 128, MM_SMEM(128)>>>(
        bufA, W1t, bufB, NNODES, DIN, H1DIM, inorm, b1);

    // ---- layer 2: GEMM2: h1@W2 -> agg2 with fused relu(*inorm+b2)+round
    mm_gemm<0,0,0,128><<<mm_grid(NNODES, H2DIM, 128), 128, MM_SMEM(128)>>>(
        bufB, W2t, bufA, NNODES, H1DIM, H2DIM, nullptr, nullptr);
    csr_agg_kernel<H2DIM, 1><<<agg_blocks, 256>>>(bufA, bufC, b2);

    // ---- layer 3: GEMM3 (NT=64): bufC@W3 -> agg3 fused *inorm+b3 -> out_h
    mm_gemm<0,0,0,64><<<mm_grid(NNODES, H3DIM, 64), 128, MM_SMEM(64)>>>(
        bufC, W3t, bufB, NNODES, H2DIM, H3DIM, nullptr, nullptr);
    csr_agg_kernel<H3DIM, 2><<<agg_blocks, 256>>>(bufB, out_h, b3);

    // ---- fused predictor: one launch for P1/P2/P3
    pred_fused<<<NROWS_PAIR / 128, 128, PF_SMEM_BYTES>>>(
        out_h, P1t, pb1, P2t, pb2, P3, pb3, psrc, pdst, nsrc, ndst, out);
}

// round 16
// speedup vs baseline: 1.0617x; 1.0617x over previous
#include <cuda_runtime.h>
#include <stdint.h>

#define NNODES 50000
#define NEDGES 800000
#define NPAIRS 200000
#define DIN    256
#define H1DIM  512
#define H2DIM  256
#define H3DIM  160
#define NROWS_PAIR (2*NPAIRS)
#define SCAN_BLOCKS ((NNODES + 255) / 256)   // 196
#define EDGE_BLOCKS ((NEDGES + 255) / 256)   // 3125

// ---------------- scratch (static device globals; no allocation) -------------
__device__ int   g_cnt[2 * NNODES];          // [0..N) out-deg, [N..2N) in-deg
__device__ float g_onorm[NNODES];
__device__ float g_inorm[NNODES];
__device__ int   g_bsum[SCAN_BLOCKS];
__device__ int   g_rowptr[NNODES + 1];
__device__ int   g_cursor[NNODES];
__device__ int   g_csr_src[NEDGES];
__device__ float g_csr_w[NEDGES];
__device__ float g_bufA[(size_t)NNODES * 512];
__device__ float g_bufB[(size_t)NNODES * 512];
__device__ float g_bufC[(size_t)NNODES * 256];
__device__ float g_Wt[512*256 + 256*512 + 160*256 + 80*160 + 40*80];

// ---------------- helpers -----------------------------------------------------
static __device__ __forceinline__ float tf32r(float x) {
    uint32_t t;
    asm("cvt.rna.tf32.f32 %0, %1;" : "=r"(t) : "f"(x));
    return __uint_as_float(t);
}
static __device__ __forceinline__ uint32_t smem_u32(const void* p) {
    uint32_t a;
    asm("{ .reg .u64 t; cvta.to.shared.u64 t, %1; cvt.u32.u64 %0, t; }" : "=r"(a) : "l"(p));
    return a;
}

// ---------------- preprocessing -----------------------------------------------
// merged launch: blocks [0, EDGE_BLOCKS) count degrees; remaining blocks
// transpose+tf32-round the 5 weight matrices (independent work, same wave).
#define TW1 (256*512)
#define TW2 (TW1 + 512*256)
#define TW3 (TW2 + 256*160)
#define TP1 (TW3 + 160*80)
#define TP2 (TP1 + 80*40)
#define TRANS_BLOCKS ((TP2 + 255) / 256)     // 901
__global__ void count_trans_kernel(const int* __restrict__ src, const int* __restrict__ dst,
                                   const float* __restrict__ W1, const float* __restrict__ W2,
                                   const float* __restrict__ W3, const float* __restrict__ P1,
                                   const float* __restrict__ P2, float* __restrict__ Wt)
{
    int b = blockIdx.x;
    if (b < EDGE_BLOCKS) {
        int i = b * 256 + threadIdx.x;
        if (i < NEDGES) {
            atomicAdd(&g_cnt[src[i]], 1);
            atomicAdd(&g_cnt[NNODES + dst[i]], 1);
        }
    } else {
        int i = (b - EDGE_BLOCKS) * 256 + threadIdx.x;
        if (i >= TP2) return;
        const float* Wsrc; int K, N, base, off;
        if (i < TW1)      { Wsrc = W1; K = 256; N = 512; base = 0;   off = i; }
        else if (i < TW2) { Wsrc = W2; K = 512; N = 256; base = TW1; off = i - TW1; }
        else if (i < TW3) { Wsrc = W3; K = 256; N = 160; base = TW2; off = i - TW2; }
        else if (i < TP1) { Wsrc = P1; K = 160; N = 80;  base = TW3; off = i - TW3; }
        else              { Wsrc = P2; K = 80;  N = 40;  base = TP1; off = i - TP1; }
        int k = off / N, n = off - k * N;
        Wt[base + n * K + k] = tf32r(Wsrc[off]);
    }
}

// phase 1: norms + per-block sums of in-degree
__global__ void scan_phase1()
{
    __shared__ int ws[8];
    int tid = threadIdx.x;
    int i = blockIdx.x * 256 + tid;
    int v = 0;
    if (i < NNODES) {
        v = g_cnt[NNODES + i];
        g_onorm[i] = rsqrtf(fmaxf((float)g_cnt[i], 1.0f));
        g_inorm[i] = rsqrtf(fmaxf((float)v, 1.0f));
    }
    int lane = tid & 31, wid = tid >> 5;
    int s = v;
    #pragma unroll
    for (int off = 16; off > 0; off >>= 1) s += __shfl_down_sync(0xFFFFFFFFu, s, off);
    if (lane == 0) ws[wid] = s;
    __syncthreads();
    if (tid == 0) {
        int t = 0;
        #pragma unroll
        for (int j = 0; j < 8; j++) t += ws[j];
        g_bsum[blockIdx.x] = t;
    }
}

// phase 2+3 merged: each block reduces g_bsum[0..bid) itself, then scans its tile
__global__ void scan_phase3()
{
    __shared__ int ws[8];
    __shared__ int rs[8];
    __shared__ int s_off;
    const int tid = threadIdx.x, bid = blockIdx.x;
    const int lane = tid & 31, wid = tid >> 5;

    int bv = (tid < bid) ? g_bsum[tid] : 0;   // bid <= 195 < 256
    int r = bv;
    #pragma unroll
    for (int off = 16; off > 0; off >>= 1) r += __shfl_down_sync(0xFFFFFFFFu, r, off);
    if (lane == 0) rs[wid] = r;
    __syncthreads();
    if (tid == 0) {
        int t = 0;
        #pragma unroll
        for (int j = 0; j < 8; j++) t += rs[j];
        s_off = t;
    }

    int i = bid * 256 + tid;
    int v = (i < NNODES) ? g_cnt[NNODES + i] : 0;
    int x = v;
    #pragma unroll
    for (int off = 1; off < 32; off <<= 1) {
        int y = __shfl_up_sync(0xFFFFFFFFu, x, off);
        if (lane >= off) x += y;
    }
    if (lane == 31) ws[wid] = x;
    __syncthreads();
    if (wid == 0) {
        int s = (lane < 8) ? ws[lane] : 0;
        #pragma unroll
        for (int off = 1; off < 8; off <<= 1) {
            int y = __shfl_up_sync(0xFFFFFFFFu, s, off);
            if (lane >= off) s += y;
        }
        if (lane < 8) ws[lane] = s;
    }
    __syncthreads();
    int base = (wid > 0) ? ws[wid - 1] : 0;
    int e = base + x - v + s_off;
    if (i < NNODES) { g_rowptr[i] = e; g_cursor[i] = e; }
    if (i == 0) g_rowptr[NNODES] = NEDGES;
}

__global__ void fill_kernel(const int* __restrict__ src, const int* __restrict__ dst,
                            const float* __restrict__ w, int E)
{
    int i = blockIdx.x * blockDim.x + threadIdx.x;
    if (i < E) {
        int s = src[i];
        int slot = atomicAdd(&g_cursor[dst[i]], 1);
        g_csr_src[slot] = s;
        g_csr_w[slot]   = w[i] * g_onorm[s];
    }
}

// ---------------- CSR aggregation with fused epilogues ------------------------
// EPI: 0 = tf32-round(acc); 1 = tf32-round(relu(acc*inorm+bias)); 2 = acc*inorm+bias
template<int D, int EPI>
__global__ void csr_agg_kernel(const float* __restrict__ feat, float* __restrict__ outp,
                               const float* __restrict__ bias)
{
    const int node = (blockIdx.x * blockDim.x + threadIdx.x) >> 5;
    const int lane = threadIdx.x & 31;
    if (node >= NNODES) return;
    const int beg = g_rowptr[node], end = g_rowptr[node + 1];

    constexpr int NV = D / 4;
    constexpr bool HAS2 = (NV > 32);
    float4 acc0 = make_float4(0.f, 0.f, 0.f, 0.f);
    float4 acc1 = make_float4(0.f, 0.f, 0.f, 0.f);
    const bool use2 = HAS2 && (lane + 32 < NV);

    for (int base = beg; base < end; base += 32) {
        int cnt = min(32, end - base);
        int   sl = (lane < cnt) ? g_csr_src[base + lane] : 0;
        float wl = (lane < cnt) ? g_csr_w [base + lane] : 0.f;
        int j = 0;
        for (; j + 4 <= cnt; j += 4) {
            int   s0 = __shfl_sync(0xFFFFFFFFu, sl, j + 0);
            int   s1 = __shfl_sync(0xFFFFFFFFu, sl, j + 1);
            int   s2 = __shfl_sync(0xFFFFFFFFu, sl, j + 2);
            int   s3 = __shfl_sync(0xFFFFFFFFu, sl, j + 3);
            float w0 = __shfl_sync(0xFFFFFFFFu, wl, j + 0);
            float w1 = __shfl_sync(0xFFFFFFFFu, wl, j + 1);
            float w2 = __shfl_sync(0xFFFFFFFFu, wl, j + 2);
            float w3 = __shfl_sync(0xFFFFFFFFu, wl, j + 3);
            const float4* r0 = (const float4*)(feat + (size_t)s0 * D);
            const float4* r1 = (const float4*)(feat + (size_t)s1 * D);
            const float4* r2 = (const float4*)(feat + (size_t)s2 * D);
            const float4* r3 = (const float4*)(feat + (size_t)s3 * D);
            if (lane < NV) {
                float4 a0 = r0[lane], a1 = r1[lane], a2 = r2[lane], a3 = r3[lane];
                acc0.x += w0*a0.x + w1*a1.x + w2*a2.x + w3*a3.x;
                acc0.y += w0*a0.y + w1*a1.y + w2*a2.y + w3*a3.y;
                acc0.z += w0*a0.z + w1*a1.z + w2*a2.z + w3*a3.z;
                acc0.w += w0*a0.w + w1*a1.w + w2*a2.w + w3*a3.w;
            }
            if (use2) {
                float4 b0 = r0[lane+32], b1 = r1[lane+32], b2 = r2[lane+32], b3 = r3[lane+32];
                acc1.x += w0*b0.x + w1*b1.x + w2*b2.x + w3*b3.x;
                acc1.y += w0*b0.y + w1*b1.y + w2*b2.y + w3*b3.y;
                acc1.z += w0*b0.z + w1*b1.z + w2*b2.z + w3*b3.z;
                acc1.w += w0*b0.w + w1*b1.w + w2*b2.w + w3*b3.w;
            }
        }
        for (; j < cnt; j++) {
            int   s  = __shfl_sync(0xFFFFFFFFu, sl, j);
            float wv = __shfl_sync(0xFFFFFFFFu, wl, j);
            const float4* row = (const float4*)(feat + (size_t)s * D);
            if (lane < NV) {
                float4 a = row[lane];
                acc0.x += wv*a.x; acc0.y += wv*a.y; acc0.z += wv*a.z; acc0.w += wv*a.w;
            }
            if (use2) {
                float4 b = row[lane+32];
                acc1.x += wv*b.x; acc1.y += wv*b.y; acc1.z += wv*b.z; acc1.w += wv*b.w;
            }
        }
    }

    float nin = (EPI >= 1) ? g_inorm[node] : 1.0f;
    float4* orow = (float4*)(outp + (size_t)node * D);
    if (lane < NV) {
        float4 v = acc0;
        if (EPI >= 1) {
            float4 bb = *(const float4*)(bias + lane * 4);
            v.x = v.x * nin + bb.x; v.y = v.y * nin + bb.y;
            v.z = v.z * nin + bb.z; v.w = v.w * nin + bb.w;
            if (EPI == 1) {
                v.x = fmaxf(v.x, 0.f); v.y = fmaxf(v.y, 0.f);
                v.z = fmaxf(v.z, 0.f); v.w = fmaxf(v.w, 0.f);
            }
        }
        if (EPI != 2) { v.x = tf32r(v.x); v.y = tf32r(v.y); v.z = tf32r(v.z); v.w = tf32r(v.w); }
        orow[lane] = v;
    }
    if (use2) {
        float4 v = acc1;
        if (EPI >= 1) {
            float4 bb = *(const float4*)(bias + (lane + 32) * 4);
            v.x = v.x * nin + bb.x; v.y = v.y * nin + bb.y;
            v.z = v.z * nin + bb.z; v.w = v.w * nin + bb.w;
            if (EPI == 1) {
                v.x = fmaxf(v.x, 0.f); v.y = fmaxf(v.y, 0.f);
                v.z = fmaxf(v.z, 0.f); v.w = fmaxf(v.w, 0.f);
            }
        }
        if (EPI != 2) { v.x = tf32r(v.x); v.y = tf32r(v.y); v.z = tf32r(v.z); v.w = tf32r(v.w); }
        orow[lane + 32] = v;
    }
}

// ---------------- tf32 mma.sync GEMM (4 warps; 2-stage double buffer — R12) ---
#define SROW 36
#define SBUF (128 * SROW)
#define MM_SMEM(NT) ((2 * SBUF + 2 * (NT) * SROW) * 4)

template<int EROW, int ACT, int ROUND, int NT>
__global__ __launch_bounds__(128)
void mm_gemm(const float* __restrict__ A, const float* __restrict__ Bt,
             float* __restrict__ C, int M, int K, int Nn,
             const float* __restrict__ escale, const float* __restrict__ cbias)
{
    constexpr int BS  = NT * SROW;
    constexpr int WNW = NT / 2;
    constexpr int NTFR = WNW / 8;
    extern __shared__ float smem[];
    float* sA = smem;                    // [2][SBUF]
    float* sB = smem + 2 * SBUF;         // [2][BS]
    const uint32_t sAu = smem_u32(sA);
    const uint32_t sBu = smem_u32(sB);

    const int tid  = threadIdx.x;
    const int m0   = blockIdx.y * 128;
    const int n0   = blockIdx.x * NT;
    const int lane = tid & 31;
    const int wq   = tid >> 5;
    const int wm   = wq & 1;
    const int wn   = wq >> 1;
    const int lr   = lane >> 2;
    const int lc   = lane & 3;
    const int sub  = lane >> 3;
    const int rr   = lane & 7;
    const int nch  = (K + 31) / 32;

    float acc[4][NTFR][4];
    #pragma unroll
    for (int mt = 0; mt < 4; mt++)
        #pragma unroll
        for (int nt = 0; nt < NTFR; nt++)
            #pragma unroll
            for (int r = 0; r < 4; r++) acc[mt][nt][r] = 0.0f;

    auto issue = [&](int c) {
        const int b = c & 1, k0 = c * 32;
        #pragma unroll
        for (int i = 0; i < 8; i++) {
            int idx = i * 128 + tid;
            int r = idx >> 3, kk = (idx & 7) * 4, gk = k0 + kk;
            uint32_t so = (uint32_t)(r * SROW + kk) * 4 + (uint32_t)b * (SBUF * 4);
            int gkc = min(gk, K - 4);
            int gm = m0 + r;
            int sz = ((gm < M) && (gk < K)) ? 16 : 0;
            const float* ga = A + (size_t)min(gm, M - 1) * K + gkc;
            asm volatile("cp.async.ca.shared.global [%0], [%1], 16, %2;"
                         :: "r"(sAu + so), "l"(ga), "r"(sz));
        }
        #pragma unroll
        for (int i = 0; i < NT / 16; i++) {
            int idx = i * 128 + tid;
            int r = idx >> 3, kk = (idx & 7) * 4, gk = k0 + kk;
            uint32_t so = (uint32_t)(r * SROW + kk) * 4 + (uint32_t)b * (BS * 4);
            int gkc = min(gk, K - 4);
            int gn = n0 + r;
            int szb = ((gn < Nn) && (gk < K)) ? 16 : 0;
            const float* gb = Bt + (size_t)min(gn, Nn - 1) * K + gkc;
            asm volatile("cp.async.ca.shared.global [%0], [%1], 16, %2;"
                         :: "r"(sBu + so), "l"(gb), "r"(szb));
        }
        asm volatile("cp.async.commit_group;" ::: "memory");
    };

    auto compute = [&](int b) {
        const uint32_t baseA = sAu + (uint32_t)b * (SBUF * 4);
        const uint32_t baseB = sBu + (uint32_t)b * (BS * 4);
        #pragma unroll
        for (int ks = 0; ks < 4; ks++) {
            const int kb = ks * 8;
            uint32_t af[4][4], bf[NTFR][2];
            #pragma unroll
            for (int mt = 0; mt < 4; mt++) {
                int row = wm * 64 + mt * 16 + rr + (sub & 1) * 8;
                int col = kb + (sub >> 1) * 4;
                uint32_t ad = baseA + (uint32_t)(row * SROW + col) * 4;
                asm volatile("ldmatrix.sync.aligned.m8n8.x4.shared.b16 {%0,%1,%2,%3}, [%4];"
                             : "=r"(af[mt][0]), "=r"(af[mt][1]), "=r"(af[mt][2]), "=r"(af[mt][3])
                             : "r"(ad));
            }
            #pragma unroll
            for (int ntp = 0; ntp < NTFR / 2; ntp++) {
                int row = wn * WNW + ntp * 16 + rr + (sub >> 1) * 8;
                int col = kb + (sub & 1) * 4;
                uint32_t bd = baseB + (uint32_t)(row * SROW + col) * 4;
                asm volatile("ldmatrix.sync.aligned.m8n8.x4.shared.b16 {%0,%1,%2,%3}, [%4];"
                             : "=r"(bf[2*ntp][0]), "=r"(bf[2*ntp][1]),
                               "=r"(bf[2*ntp+1][0]), "=r"(bf[2*ntp+1][1])
                             : "r"(bd));
            }
            #pragma unroll
            for (int mt = 0; mt < 4; mt++)
                #pragma unroll
                for (int nt = 0; nt < NTFR; nt++)
                    asm volatile(
                        "mma.sync.aligned.m16n8k8.row.col.f32.tf32.tf32.f32 "
                        "{%0,%1,%2,%3}, {%4,%5,%6,%7}, {%8,%9}, {%0,%1,%2,%3};"
                        : "+f"(acc[mt][nt][0]), "+f"(acc[mt][nt][1]),
                          "+f"(acc[mt][nt][2]), "+f"(acc[mt][nt][3])
                        : "r"(af[mt][0]), "r"(af[mt][1]), "r"(af[mt][2]), "r"(af[mt][3]),
                          "r"(bf[nt][0]), "r"(bf[nt][1]));
        }
    };

    issue(0);
    for (int c = 0; c < nch; c++) {
        if (c + 1 < nch) {
            issue(c + 1);
            asm volatile("cp.async.wait_group 1;" ::: "memory");
        } else {
            asm volatile("cp.async.wait_group 0;" ::: "memory");
        }
        __syncthreads();
        compute(c & 1);
        __syncthreads();
    }

    #pragma unroll
    for (int mt = 0; mt < 4; mt++) {
        int r0 = m0 + wm * 64 + mt * 16 + lr;
        int r1 = r0 + 8;
        float s0 = 1.f, s1 = 1.f;
        if (EROW) {
            if (r0 < M) s0 = escale[r0];
            if (r1 < M) s1 = escale[r1];
        }
        #pragma unroll
        for (int nt = 0; nt < NTFR; nt++) {
            int col = n0 + wn * WNW + nt * 8 + lc * 2;
            if (col >= Nn) continue;
            float bx = 0.f, by = 0.f;
            if (cbias) { bx = cbias[col]; by = cbias[col + 1]; }
            #pragma unroll
            for (int half = 0; half < 2; half++) {
                int row = half ? r1 : r0;
                if (row >= M) continue;
                float sc = half ? s1 : s0;
                float vx = acc[mt][nt][half * 2 + 0] * sc + bx;
                float vy = acc[mt][nt][half * 2 + 1] * sc + by;
                if (ACT == 1) { vx = fmaxf(vx, 0.f); vy = fmaxf(vy, 0.f); }
                else if (ACT == 2) {
                    vx = (vx > 0.f) ? vx : 0.2f * vx;
                    vy = (vy > 0.f) ? vy : 0.2f * vy;
                }
                if (ROUND) { vx = tf32r(vx); vy = tf32r(vy); }
                *(float2*)(C + (size_t)row * Nn + col) = make_float2(vx, vy);
            }
        }
    }
}

// ---------------- fused predictor: pair-gather -> 160->80 -> 80->40 -> 40->1 --
#define PF_CH (128 * 36)
#define PF_SMEM_BYTES (5 * PF_CH * 4)   // 92160

__global__ __launch_bounds__(128)
void pred_fused(const float* __restrict__ h3,
                const float* __restrict__ P1t, const float* __restrict__ pb1,
                const float* __restrict__ P2t, const float* __restrict__ pb2,
                const float* __restrict__ P3,  const float* __restrict__ pb3,
                const int* __restrict__ ips, const int* __restrict__ ipd,
                const int* __restrict__ ins, const int* __restrict__ ind,
                float* __restrict__ out)
{
    extern __shared__ float smem[];
    float* sAd = smem;                 // [2][PF_CH]
    float* s1o = smem + 2 * PF_CH;     // [3][PF_CH]
    float* s2o = smem;                 // alias over sAd
    const uint32_t sAu = smem_u32(sAd);
    const uint32_t s1u = smem_u32(s1o);

    const int tid  = threadIdx.x;
    const int r0   = blockIdx.x * 128;
    const int lane = tid & 31;
    const int wq   = tid >> 5;
    const int wm   = wq & 1;
    const int wn   = wq >> 1;
    const int lr   = lane >> 2;
    const int lc   = lane & 3;
    const int sub  = lane >> 3;
    const int rr   = lane & 7;

    float4 rgA[8];
    auto fetchA = [&](int c) {
        const int k0 = c * 32;
        #pragma unroll
        for (int i = 0; i < 8; i++) {
            int idx = i * 128 + tid;
            int r = idx >> 3, kk = (idx & 7) * 4;
            int gm = r0 + r;
            int ia, ib;
            if (gm < NPAIRS) { ia = ips[gm]; ib = ipd[gm]; }
            else             { ia = ins[gm - NPAIRS]; ib = ind[gm - NPAIRS]; }
            float4 va = *(const float4*)(h3 + (size_t)ia * H3DIM + k0 + kk);
            float4 vb = *(const float4*)(h3 + (size_t)ib * H3DIM + k0 + kk);
            rgA[i] = make_float4(va.x*vb.x, va.y*vb.y, va.z*vb.z, va.w*vb.w);
        }
    };
    auto storeA = [&](int b) {
        #pragma unroll
        for (int i = 0; i < 8; i++) {
            int idx = i * 128 + tid;
            int r = idx >> 3, kk = (idx & 7) * 4;
            float4 v = rgA[i];
            v.x = tf32r(v.x); v.y = tf32r(v.y); v.z = tf32r(v.z); v.w = tf32r(v.w);
            *(float4*)(sAd + b * PF_CH + r * 36 + kk) = v;
        }
    };

    float a1[4][5][4];
    #pragma unroll
    for (int mt = 0; mt < 4; mt++)
        #pragma unroll
        for (int nt = 0; nt < 5; nt++)
            #pragma unroll
            for (int r = 0; r < 4; r++) a1[mt][nt][r] = 0.0f;

    auto compute1 = [&](int b, int c) {
        const uint32_t baseA = sAu + (uint32_t)b * (PF_CH * 4);
        #pragma unroll
        for (int ks = 0; ks < 4; ks++) {
            const int kb = ks * 8;
            const int kg = c * 32 + kb;
            uint32_t af[4][4], bf[5][2];
            #pragma unroll
            for (int mt = 0; mt < 4; mt++) {
                int row = wm * 64 + mt * 16 + rr + (sub & 1) * 8;
                int col = kb + (sub >> 1) * 4;
                uint32_t ad = baseA + (uint32_t)(row * 36 + col) * 4;
                asm volatile("ldmatrix.sync.aligned.m8n8.x4.shared.b16 {%0,%1,%2,%3}, [%4];"
                             : "=r"(af[mt][0]), "=r"(af[mt][1]), "=r"(af[mt][2]), "=r"(af[mt][3])
                             : "r"(ad));
            }
            #pragma unroll
            for (int nt = 0; nt < 5; nt++) {
                int n = wn * 40 + nt * 8 + lr;
                const float* bp = P1t + n * 160 + kg + lc;
                bf[nt][0] = __float_as_uint(__ldg(bp));
                bf[nt][1] = __float_as_uint(__ldg(bp + 4));
            }
            #pragma unroll
            for (int mt = 0; mt < 4; mt++)
                #pragma unroll
                for (int nt = 0; nt < 5; nt++)
                    asm volatile(
                        "mma.sync.aligned.m16n8k8.row.col.f32.tf32.tf32.f32 "
                        "{%0,%1,%2,%3}, {%4,%5,%6,%7}, {%8,%9}, {%0,%1,%2,%3};"
                        : "+f"(a1[mt][nt][0]), "+f"(a1[mt][nt][1]),
                          "+f"(a1[mt][nt][2]), "+f"(a1[mt][nt][3])
                        : "r"(af[mt][0]), "r"(af[mt][1]), "r"(af[mt][2]), "r"(af[mt][3]),
                          "r"(bf[nt][0]), "r"(bf[nt][1]));
        }
    };

    fetchA(0);
    storeA(0);
    for (int c = 0; c < 5; c++) {
        __syncthreads();
        if (c + 1 < 5) fetchA(c + 1);
        compute1(c & 1, c);
        if (c + 1 < 5) {
            __syncthreads();
            storeA((c + 1) & 1);
        }
    }

    #pragma unroll
    for (int mt = 0; mt < 4; mt++) {
        int row0 = wm * 64 + mt * 16 + lr;
        #pragma unroll
        for (int nt = 0; nt < 5; nt++) {
            int col = wn * 40 + nt * 8 + lc * 2;
            float bx = pb1[col], by = pb1[col + 1];
            int ch = col >> 5, ci = col & 31;
            #pragma unroll
            for (int half = 0; half < 2; half++) {
                int row = row0 + half * 8;
                float vx = a1[mt][nt][half * 2 + 0] + bx;
                float vy = a1[mt][nt][half * 2 + 1] + by;
                vx = (vx > 0.f) ? vx : 0.2f * vx;
                vy = (vy > 0.f) ? vy : 0.2f * vy;
                vx = tf32r(vx); vy = tf32r(vy);
                *(float2*)(s1o + ch * PF_CH + row * 36 + ci) = make_float2(vx, vy);
            }
        }
    }
    __syncthreads();

    float a2[2][5][4];
    #pragma unroll
    for (int mt = 0; mt < 2; mt++)
        #pragma unroll
        for (int nt = 0; nt < 5; nt++)
            #pragma unroll
            for (int r = 0; r < 4; r++) a2[mt][nt][r] = 0.0f;

    #pragma unroll
    for (int ch = 0; ch < 3; ch++) {
        const int nks = (ch < 2) ? 4 : 2;
        const uint32_t baseA = s1u + (uint32_t)ch * (PF_CH * 4);
        for (int ks = 0; ks < nks; ks++) {
            const int kb = ks * 8;
            const int kg = ch * 32 + kb;
            uint32_t af[2][4], bf[5][2];
            #pragma unroll
            for (int mt = 0; mt < 2; mt++) {
                int row = wq * 32 + mt * 16 + rr + (sub & 1) * 8;
                int col = kb + (sub >> 1) * 4;
                uint32_t ad = baseA + (uint32_t)(row * 36 + col) * 4;
                asm volatile("ldmatrix.sync.aligned.m8n8.x4.shared.b16 {%0,%1,%2,%3}, [%4];"
                             : "=r"(af[mt][0]), "=r"(af[mt][1]), "=r"(af[mt][2]), "=r"(af[mt][3])
                             : "r"(ad));
            }
            #pragma unroll
            for (int nt = 0; nt < 5; nt++) {
                int n = nt * 8 + lr;
                const float* bp = P2t + n * 80 + kg + lc;
                bf[nt][0] = __float_as_uint(__ldg(bp));
                bf[nt][1] = __float_as_uint(__ldg(bp + 4));
            }
            #pragma unroll
            for (int mt = 0; mt < 2; mt++)
                #pragma unroll
                for (int nt = 0; nt < 5; nt++)
                    asm volatile(
                        "mma.sync.aligned.m16n8k8.row.col.f32.tf32.tf32.f32 "
                        "{%0,%1,%2,%3}, {%4,%5,%6,%7}, {%8,%9}, {%0,%1,%2,%3};"
                        : "+f"(a2[mt][nt][0]), "+f"(a2[mt][nt][1]),
                          "+f"(a2[mt][nt][2]), "+f"(a2[mt][nt][3])
                        : "r"(af[mt][0]), "r"(af[mt][1]), "r"(af[mt][2]), "r"(af[mt][3]),
                          "r"(bf[nt][0]), "r"(bf[nt][1]));
        }
    }

    #pragma unroll
    for (int mt = 0; mt < 2; mt++) {
        int row0 = wq * 32 + mt * 16 + lr;
        #pragma unroll
        for (int nt = 0; nt < 5; nt++) {
            int col = nt * 8 + lc * 2;
            float bx = pb2[col], by = pb2[col + 1];
            #pragma unroll
            for (int half = 0; half < 2; half++) {
                int row = row0 + half * 8;
                float vx = a2[mt][nt][half * 2 + 0] + bx;
                float vy = a2[mt][nt][half * 2 + 1] + by;
                vx = (vx > 0.f) ? vx : 0.2f * vx;
                vy = (vy > 0.f) ? vy : 0.2f * vy;
                *(float2*)(s2o + row * 44 + col) = make_float2(vx, vy);
            }
        }
    }
    __syncthreads();

    float acc = __ldg(pb3);
    const float* rowp = s2o + tid * 44;
    #pragma unroll
    for (int k = 0; k < 40; k += 4) {
        float4 v = *(const float4*)(rowp + k);
        acc += v.x * __ldg(P3 + k + 0) + v.y * __ldg(P3 + k + 1)
             + v.z * __ldg(P3 + k + 2) + v.w * __ldg(P3 + k + 3);
    }
    out[r0 + tid] = acc;
}

// ---------------- launch ------------------------------------------------------
static inline dim3 mm_grid(int M, int Nn, int nt) { return dim3((Nn + nt - 1) / nt, (M + 127) / 128); }

extern "C" void kernel_launch(void* const* d_in, const int* in_sizes, int n_in,
                              void* d_out, int out_size)
{
    const float* x   = (const float*)d_in[0];
    const float* w   = (const float*)d_in[1];
    const int* src   = (const int*)d_in[2];
    const int* dst   = (const int*)d_in[3];
    const int* psrc  = (const int*)d_in[4];
    const int* pdst  = (const int*)d_in[5];
    const int* nsrc  = (const int*)d_in[6];
    const int* ndst  = (const int*)d_in[7];
    const float* W1  = (const float*)d_in[8];
    const float* b1  = (const float*)d_in[9];
    const float* W2  = (const float*)d_in[10];
    const float* b2  = (const float*)d_in[11];
    const float* W3  = (const float*)d_in[12];
    const float* b3  = (const float*)d_in[13];
    const float* P1  = (const float*)d_in[14];
    const float* pb1 = (const float*)d_in[15];
    const float* P2  = (const float*)d_in[16];
    const float* pb2 = (const float*)d_in[17];
    const float* P3  = (const float*)d_in[18];
    const float* pb3 = (const float*)d_in[19];

    float* out = (float*)d_out;
    float* out_h = out + NROWS_PAIR;   // [NPAIR pos | NPAIR neg | N*160 h]

    void *p_cnt, *p_inorm, *p_bufA, *p_bufB, *p_bufC, *p_Wt;
    cudaGetSymbolAddress(&p_cnt,   g_cnt);
    cudaGetSymbolAddress(&p_inorm, g_inorm);
    cudaGetSymbolAddress(&p_bufA,  g_bufA);
    cudaGetSymbolAddress(&p_bufB,  g_bufB);
    cudaGetSymbolAddress(&p_bufC,  g_bufC);
    cudaGetSymbolAddress(&p_Wt,    g_Wt);
    float* inorm = (float*)p_inorm;
    float* bufA = (float*)p_bufA;
    float* bufB = (float*)p_bufB;
    float* bufC = (float*)p_bufC;
    float* W1t = (float*)p_Wt;
    float* W2t = W1t + 512 * 256;
    float* W3t = W2t + 256 * 512;
    float* P1t = W3t + 160 * 256;
    float* P2t = P1t + 80 * 160;

    cudaFuncSetAttribute(mm_gemm<1,1,1,128>, cudaFuncAttributeMaxDynamicSharedMemorySize, MM_SMEM(128));
    cudaFuncSetAttribute(mm_gemm<0,0,0,128>, cudaFuncAttributeMaxDynamicSharedMemorySize, MM_SMEM(128));
    cudaFuncSetAttribute(mm_gemm<0,0,0,64>,  cudaFuncAttributeMaxDynamicSharedMemorySize, MM_SMEM(64));
    cudaFuncSetAttribute(pred_fused, cudaFuncAttributeMaxDynamicSharedMemorySize, PF_SMEM_BYTES);

    const int E = NEDGES;

    // ---- preprocessing: one memset; count+transpose merged; 2-kernel scan; fill
    cudaMemsetAsync(p_cnt, 0, 2 * NNODES * sizeof(int));
    count_trans_kernel<<<EDGE_BLOCKS + TRANS_BLOCKS, 256>>>(
        src, dst, W1, W2, W3, P1, P2, (float*)p_Wt);
    scan_phase1<<<SCAN_BLOCKS, 256>>>();
    scan_phase3<<<SCAN_BLOCKS, 256>>>();
    fill_kernel<<<(E + 255) / 256, 256>>>(src, dst, w, E);

    const int agg_blocks = (NNODES * 32 + 255) / 256;

    // ---- layer 1: agg(x) [round] -> GEMM1: @W1, *inorm+b1, relu, round
    csr_agg_kernel<DIN, 0><<<agg_blocks, 256>>>(x, bufA, nullptr);
    mm_gemm<1,1,1,128><<<mm_grid(NNODES, H1DIM, 128), 128, MM_SMEM(128)>>>(
        bufA, W1t, bufB, NNODES, DIN, H1DIM, inorm, b1);

    // ---- layer 2: GEMM2: h1@W2 -> agg2 with fused relu(*inorm+b2)+round
    mm_gemm<0,0,0,128><<<mm_grid(NNODES, H2DIM, 128), 128, MM_SMEM(128)>>>(
        bufB, W2t, bufA, NNODES, H1DIM, H2DIM, nullptr, nullptr);
    csr_agg_kernel<H2DIM, 1><<<agg_blocks, 256>>>(bufA, bufC, b2);

    // ---- layer 3: GEMM3 (NT=64): bufC@W3 -> agg3 fused *inorm+b3 -> out_h
    mm_gemm<0,0,0,64><<<mm_grid(NNODES, H3DIM, 64), 128, MM_SMEM(64)>>>(
        bufC, W3t, bufB, NNODES, H2DIM, H3DIM, nullptr, nullptr);
    csr_agg_kernel<H3DIM, 2><<<agg_blocks, 256>>>(bufB, out_h, b3);

    // ---- fused predictor: one launch for P1/P2/P3
    pred_fused<<<NROWS_PAIR / 128, 128, PF_SMEM_BYTES>>>(
        out_h, P1t, pb1, P2t, pb2, P3, pb3, psrc, pdst, nsrc, ndst, out);
}